// round 15
// baseline (speedup 1.0000x reference)
#include <cuda_runtime.h>
#include <cuda_bf16.h>
#include <cstdint>

#define S_TOK 8192
#define D_DIM 2048
#define E_EXP 64
#define CAP   128

// ---------------- scratch ----------------
__device__ int   g_idx[S_TOK];
__device__ float g_gate1[S_TOK];
__device__ int   g_rank[S_TOK];                   // intra-tile rank within expert queue
__device__ int   g_cnt[128 * E_EXP];              // per-tile expert histogram
__device__ float g_partialGateSum[128 * E_EXP];   // per-tile softmax expert sums
__device__ __nv_bfloat16 g_wgh[E_EXP * D_DIM];    // pre-split weights (hi)
__device__ __nv_bfloat16 g_wgl[E_EXP * D_DIM];    // pre-split weights (lo)

// ---------------- helpers ----------------
__device__ __forceinline__ void mma_bf16(float c[4], uint32_t a0, uint32_t a1, uint32_t a2, uint32_t a3,
                                         uint32_t b0, uint32_t b1) {
    asm volatile(
        "mma.sync.aligned.m16n8k16.row.col.f32.bf16.bf16.f32 "
        "{%0,%1,%2,%3}, {%4,%5,%6,%7}, {%8,%9}, {%0,%1,%2,%3};"
        : "+f"(c[0]), "+f"(c[1]), "+f"(c[2]), "+f"(c[3])
        : "r"(a0), "r"(a1), "r"(a2), "r"(a3), "r"(b0), "r"(b1));
}
__device__ __forceinline__ void split_bf16(float f, uint16_t& h, uint16_t& l) {
    __nv_bfloat16 bh = __float2bfloat16(f);
    float rem = f - __bfloat162float(bh);
    __nv_bfloat16 bl = __float2bfloat16(rem);
    h = __bfloat16_as_ushort(bh);
    l = __bfloat16_as_ushort(bl);
}
__device__ __forceinline__ uint64_t pack4(uint16_t a, uint16_t b, uint16_t c, uint16_t d) {
    return (uint64_t)a | ((uint64_t)b << 16) | ((uint64_t)c << 32) | ((uint64_t)d << 48);
}

// ================= K0: pre-split wg into bf16 hi/lo =================
__global__ void __launch_bounds__(256) split_wg_kernel(const float* __restrict__ wg) {
    const int i = (blockIdx.x * 256 + threadIdx.x) * 4;   // 128 x 256 x 4 = 131072
    float4 v = *(const float4*)(wg + i);
    uint16_t h0, l0, h1, l1, h2, l2, h3, l3;
    split_bf16(v.x, h0, l0); split_bf16(v.y, h1, l1);
    split_bf16(v.z, h2, l2); split_bf16(v.w, h3, l3);
    ((uint64_t*)g_wgh)[i >> 2] = pack4(h0, h1, h2, h3);
    ((uint64_t*)g_wgl)[i >> 2] = pack4(l0, l1, l2, l3);
}

// ================= K1: single-wave fused GEMM + zeroing (148 blocks) =================
// Blocks 0..63  : gemm role, 2 M-tiles each (tiles t and t+64), then zero last-10% chunk
// Blocks 64..147: zero role, contiguous ~90%/84 chunk each (runs for the whole gemm)
#define GEMM_BLOCKS 64
#define TOT_BLOCKS  148
#define NTILE  128
#define KC     64
#define NCH_G  16                   // chunks per warp group
#define SROWH  72                   // padded row: 72 bf16 = 144B
#define TILE_B (64 * SROWH * 2)     // 9216 B per tile
#define OFF_AH 0
#define OFF_AL (TILE_B)
#define OFF_BH (2 * TILE_B)
#define OFF_BL (3 * TILE_B)
#define BUFSET (4 * TILE_B)         // 36864 per group
#define SM_DYN (2 * BUFSET)         // 73728

__global__ void __launch_bounds__(512) fused_gemm_zero_kernel(const float* __restrict__ x,
                                                              float* __restrict__ out,
                                                              long long out_elems) {
    const long long total4 = out_elems >> 2;
    const long long ZG4    = total4 / (64 * 10);            // per-gemm-block chunk (~10%/64)
    const long long C4     = total4 - 64 * ZG4;             // zero-role boundary

    // ---------- zero role (84 blocks): contiguous chunks of first C4 float4s ----------
    if (blockIdx.x >= GEMM_BLOCKS) {
        const long long k  = blockIdx.x - GEMM_BLOCKS;      // 0..83
        const long long Z4 = (C4 + 83) / 84;
        const long long beg = k * Z4;
        const long long end = (beg + Z4 < C4) ? beg + Z4 : C4;
        float4* o4 = (float4*)out;
        const float4 z = make_float4(0.f, 0.f, 0.f, 0.f);
        for (long long i = beg + threadIdx.x; i < end; i += 512) o4[i] = z;
        if (k == 0 && threadIdx.x == 0)
            for (long long i = total4 * 4; i < out_elems; i++) out[i] = 0.f;
        return;
    }

    // ---------- gemm role: 2 tiles sequentially ----------
    extern __shared__ __align__(16) char smbuf[];

    const int tid  = threadIdx.x;
    const int lane = tid & 31;
    const int w    = tid >> 5;
    const int g    = w >> 3;            // warp group 0/1 (K-split)
    const int wg_  = w & 7;
    const int gtid = tid & 255;
    const int M0   = (wg_ & 3) * 16;
    const int N0   = (wg_ >> 2) * 32;

    int rr[4], cc[4];
#pragma unroll
    for (int t = 0; t < 4; t++) { int f = gtid + t * 256; rr[t] = f >> 4; cc[t] = (f & 15) * 4; }
    int br[2], b8[2];
#pragma unroll
    for (int t = 0; t < 2; t++) { int u = gtid + t * 256; br[t] = u >> 3; b8[t] = u & 7; }

    char* mybuf = smbuf + g * BUFSET;
    const uint32_t* AH32 = (const uint32_t*)(mybuf + OFF_AH);
    const uint32_t* AL32 = (const uint32_t*)(mybuf + OFF_AL);
    const uint32_t* BH32 = (const uint32_t*)(mybuf + OFF_BH);
    const uint32_t* BL32 = (const uint32_t*)(mybuf + OFF_BL);
    const uint4* WH4 = (const uint4*)g_wgh;
    const uint4* WL4 = (const uint4*)g_wgl;

    for (int tt = blockIdx.x; tt < NTILE; tt += GEMM_BLOCKS) {
        const int m0 = tt * 64;

        float acc[4][4];
#pragma unroll
        for (int nt = 0; nt < 4; nt++)
#pragma unroll
            for (int j = 0; j < 4; j++) acc[nt][j] = 0.0f;

        float4 av[4];
        uint4  bvh[2], bvl[2];
        {
            const int kc = g * KC;
#pragma unroll
            for (int t = 0; t < 4; t++)
                av[t] = *(const float4*)(x + (size_t)(m0 + rr[t]) * D_DIM + kc + cc[t]);
#pragma unroll
            for (int t = 0; t < 2; t++) {
                bvh[t] = WH4[br[t] * (D_DIM / 8) + (kc >> 3) + b8[t]];
                bvl[t] = WL4[br[t] * (D_DIM / 8) + (kc >> 3) + b8[t]];
            }
        }

        for (int it = 0; it < NCH_G; it++) {
#pragma unroll
            for (int t = 0; t < 4; t++) {
                uint16_t h0, l0, h1, l1, h2, l2, h3, l3;
                const uint32_t off = (uint32_t)(rr[t] * SROWH + cc[t]) * 2;
                split_bf16(av[t].x, h0, l0); split_bf16(av[t].y, h1, l1);
                split_bf16(av[t].z, h2, l2); split_bf16(av[t].w, h3, l3);
                *(uint64_t*)(mybuf + OFF_AH + off) = pack4(h0, h1, h2, h3);
                *(uint64_t*)(mybuf + OFF_AL + off) = pack4(l0, l1, l2, l3);
            }
#pragma unroll
            for (int t = 0; t < 2; t++) {
                const uint32_t off = (uint32_t)(br[t] * SROWH) * 2 + b8[t] * 16;
                *(uint4*)(mybuf + OFF_BH + off) = bvh[t];
                *(uint4*)(mybuf + OFF_BL + off) = bvl[t];
            }
            __syncthreads();

            if (it + 1 < NCH_G) {
                const int kc = (2 * (it + 1) + g) * KC;
#pragma unroll
                for (int t = 0; t < 4; t++)
                    av[t] = *(const float4*)(x + (size_t)(m0 + rr[t]) * D_DIM + kc + cc[t]);
#pragma unroll
                for (int t = 0; t < 2; t++) {
                    bvh[t] = WH4[br[t] * (D_DIM / 8) + (kc >> 3) + b8[t]];
                    bvl[t] = WL4[br[t] * (D_DIM / 8) + (kc >> 3) + b8[t]];
                }
            }

#pragma unroll
            for (int ks = 0; ks < 4; ks++) {
                const int kq = ks * 16 + (lane & 3) * 2;
                const int mA = M0 + (lane >> 2);
                const uint32_t ah0 = AH32[(mA * SROWH + kq) >> 1];
                const uint32_t ah1 = AH32[((mA + 8) * SROWH + kq) >> 1];
                const uint32_t ah2 = AH32[(mA * SROWH + kq + 8) >> 1];
                const uint32_t ah3 = AH32[((mA + 8) * SROWH + kq + 8) >> 1];
                const uint32_t al0 = AL32[(mA * SROWH + kq) >> 1];
                const uint32_t al1 = AL32[((mA + 8) * SROWH + kq) >> 1];
                const uint32_t al2 = AL32[(mA * SROWH + kq + 8) >> 1];
                const uint32_t al3 = AL32[((mA + 8) * SROWH + kq + 8) >> 1];
#pragma unroll
                for (int nt = 0; nt < 4; nt++) {
                    const int nB = N0 + nt * 8 + (lane >> 2);
                    const uint32_t bh0 = BH32[(nB * SROWH + kq) >> 1];
                    const uint32_t bh1 = BH32[(nB * SROWH + kq + 8) >> 1];
                    const uint32_t bl0 = BL32[(nB * SROWH + kq) >> 1];
                    const uint32_t bl1 = BL32[(nB * SROWH + kq + 8) >> 1];
                    mma_bf16(acc[nt], ah0, ah1, ah2, ah3, bh0, bh1);
                    mma_bf16(acc[nt], ah0, ah1, ah2, ah3, bl0, bl1);
                    mma_bf16(acc[nt], al0, al1, al2, al3, bh0, bh1);
                    mma_bf16(acc[nt], al0, al1, al2, al3, bl0, bl1);
                }
            }
            __syncthreads();
        }

        // ---------- combine groups + softmax + rank/hist epilogue ----------
        float* Ls  = (float*)smbuf;            // [64][65]
        float* pg  = Ls + 64 * 65;             // [64][65]
        float* red = pg + 64 * 65;             // [8][64]
        int*   hw  = (int*)(red + 8 * 64);     // [2][64]

        const int r0 = M0 + (lane >> 2);
        const int cb = (lane & 3) * 2;
        if (g == 0) {
#pragma unroll
            for (int nt = 0; nt < 4; nt++) {
                const int c0 = N0 + nt * 8 + cb;
                Ls[r0 * 65 + c0]           = acc[nt][0];
                Ls[r0 * 65 + c0 + 1]       = acc[nt][1];
                Ls[(r0 + 8) * 65 + c0]     = acc[nt][2];
                Ls[(r0 + 8) * 65 + c0 + 1] = acc[nt][3];
            }
        }
        __syncthreads();
        if (g == 1) {
#pragma unroll
            for (int nt = 0; nt < 4; nt++) {
                const int c0 = N0 + nt * 8 + cb;
                Ls[r0 * 65 + c0]           += acc[nt][0];
                Ls[r0 * 65 + c0 + 1]       += acc[nt][1];
                Ls[(r0 + 8) * 65 + c0]     += acc[nt][2];
                Ls[(r0 + 8) * 65 + c0 + 1] += acc[nt][3];
            }
        }
        __syncthreads();

        int mi = 0;
        if (tid < 64) {
            float mv = -3.4e38f;
#pragma unroll
            for (int e = 0; e < 64; e++) {
                float v = Ls[tid * 65 + e];
                if (v > mv) { mv = v; mi = e; }     // first-occurrence argmax
            }
            float sum = 0.0f;
            float ev[64];
#pragma unroll
            for (int e = 0; e < 64; e++) { ev[e] = expf(Ls[tid * 65 + e] - mv); sum += ev[e]; }
            const float inv = 1.0f / sum;
            g_idx[m0 + tid]   = mi;
            g_gate1[m0 + tid] = inv;
#pragma unroll
            for (int e = 0; e < 64; e++) pg[tid * 65 + e] = ev[e] * inv;
        }
        if (tid < 128) hw[tid] = 0;
        __syncthreads();

        int rank = 0;
        if (tid < 64) {
            unsigned mm = __match_any_sync(0xffffffffu, mi);
            rank = __popc(mm & ((1u << lane) - 1u));
            if (lane == __ffs(mm) - 1) hw[(tid >> 5) * 64 + mi] = __popc(mm);
        }
        __syncthreads();
        if (tid < 64) {
            if (tid >= 32) rank += hw[mi];
            g_rank[m0 + tid] = rank;
            g_cnt[tt * 64 + tid] = hw[tid] + hw[64 + tid];
        }

        {
            const int e = tid & 63, r = tid >> 6;
            float s2 = 0.0f;
#pragma unroll
            for (int j = 0; j < 8; j++) s2 += pg[(r * 8 + j) * 65 + e];
            red[r * 64 + e] = s2;
        }
        __syncthreads();
        if (tid < 64) {
            float s = 0.0f;
#pragma unroll
            for (int r = 0; r < 8; r++) s += red[r * 64 + tid];
            g_partialGateSum[(size_t)tt * 64 + tid] = s;
        }
        __syncthreads();   // smem reused by next tile's staging
    }

    // ---------- gemm blocks zero the last-10% tail ----------
    {
        float4* o4 = (float4*)out;
        const float4 z = make_float4(0.f, 0.f, 0.f, 0.f);
        const long long beg = C4 + (long long)blockIdx.x * ZG4;
        const long long end = beg + ZG4;
        for (long long i = beg + threadIdx.x; i < end; i += 512) o4[i] = z;
    }
}

// ================= K2: prefix + aux + scatter (1 block; zeros already done) =================
__global__ void __launch_bounds__(1024) scan_scatter_kernel(float* __restrict__ combine,
                                                            float* __restrict__ maskp,
                                                            float* __restrict__ lauxp) {
    __shared__ int   bases[128 * E_EXP];   // 32 KB: global base per (tile, expert)
    __shared__ int   ss[16 * E_EXP];
    __shared__ float ps[16 * E_EXP];
    __shared__ int   cntS[E_EXP];
    __shared__ float vals[E_EXP];

    const int tid = threadIdx.x;
    const int e = tid & 63, r = tid >> 6;       // 16 slices x 8 tiles

    // ---- prefetch token data for scatter (independent LDGs, high MLP) ----
    int eA[8], rkA[8];
    float gA[8];
#pragma unroll
    for (int j = 0; j < 8; j++) eA[j]  = g_idx[tid + j * 1024];
#pragma unroll
    for (int j = 0; j < 8; j++) rkA[j] = g_rank[tid + j * 1024];
#pragma unroll
    for (int j = 0; j < 8; j++) gA[j]  = g_gate1[tid + j * 1024];

    int c[8], pre[8];
    float p[8];
#pragma unroll
    for (int j = 0; j < 8; j++) c[j] = g_cnt[(r * 8 + j) * 64 + e];
#pragma unroll
    for (int j = 0; j < 8; j++) p[j] = g_partialGateSum[(size_t)(r * 8 + j) * 64 + e];

    int s = 0;
#pragma unroll
    for (int j = 0; j < 8; j++) { pre[j] = s; s += c[j]; }
    ss[r * 64 + e] = s;
    float fs = 0.0f;
#pragma unroll
    for (int j = 0; j < 8; j++) fs += p[j];
    ps[r * 64 + e] = fs;
    __syncthreads();

    if (tid < 64) {
        int running = 0;
        for (int rr = 0; rr < 16; rr++) {
            int t = ss[rr * 64 + tid];
            ss[rr * 64 + tid] = running;
            running += t;
        }
        cntS[tid] = running;
    }
    __syncthreads();

    const int base0 = ss[r * 64 + e];
#pragma unroll
    for (int j = 0; j < 8; j++) bases[(r * 8 + j) * 64 + e] = base0 + pre[j];

    if (tid < 64) {
        float me = 0.0f;
#pragma unroll
        for (int rr = 0; rr < 16; rr++) me += ps[rr * 64 + tid];
        me /= (float)S_TOK;
        float ce = (float)cntS[tid] / (float)S_TOK;
        vals[tid] = me * ce;
    }
    __syncthreads();

    // ---- scatter ----
#pragma unroll
    for (int j = 0; j < 8; j++) {
        const int stok = tid + j * 1024;
        const int ee   = eA[j];
        const int loc  = bases[(stok >> 6) * 64 + ee] + rkA[j];
        if (loc < CAP) {
            const size_t off = (size_t)stok * (E_EXP * CAP) + (size_t)ee * CAP + loc;
            combine[off] = gA[j];
            if (maskp) maskp[off] = 1.0f;
        }
    }

    if (tid == 0 && lauxp) {
        float a = 0.0f;
        for (int ee = 0; ee < E_EXP; ee++) a += vals[ee];
        lauxp[0] = a * (float)E_EXP;            // mean * E*E == sum * E
    }
}

// ---------------- launch ----------------
extern "C" void kernel_launch(void* const* d_in, const int* in_sizes, int n_in,
                              void* d_out, int out_size) {
    const float* x  = (const float*)d_in[0];   // [S, D]
    const float* wg = (const float*)d_in[1];   // [E, D]
    float* out = (float*)d_out;

    const long long SEC = (long long)S_TOK * E_EXP * CAP;  // 67,108,864
    float* lauxp   = nullptr;
    float* combine = out;
    float* maskp   = nullptr;
    if ((long long)out_size >= 1 + 2 * SEC) {          // [l_aux, combine, mask]
        lauxp = out; combine = out + 1; maskp = out + 1 + SEC;
    } else if ((long long)out_size == 1 + SEC) {       // [l_aux, combine]
        lauxp = out; combine = out + 1;
    }

    cudaFuncSetAttribute(fused_gemm_zero_kernel, cudaFuncAttributeMaxDynamicSharedMemorySize, SM_DYN);

    split_wg_kernel<<<128, 256>>>(wg);
    fused_gemm_zero_kernel<<<TOT_BLOCKS, 512, SM_DYN>>>(x, out, (long long)out_size);
    scan_scatter_kernel<<<1, 1024>>>(combine, maskp, lauxp);
}

// round 16
// speedup vs baseline: 1.0031x; 1.0031x over previous
#include <cuda_runtime.h>
#include <cuda_bf16.h>
#include <cstdint>

#define S_TOK 8192
#define D_DIM 2048
#define E_EXP 64
#define CAP   128

// ---------------- scratch ----------------
__device__ int   g_idx[S_TOK];
__device__ float g_gate1[S_TOK];
__device__ int   g_rank[S_TOK];                   // intra-tile rank within expert queue
__device__ int   g_cnt[128 * E_EXP];              // per-tile expert histogram
__device__ float g_partialGateSum[128 * E_EXP];   // per-tile softmax expert sums
__device__ __nv_bfloat16 g_wgh[E_EXP * D_DIM];    // pre-split weights (hi)
__device__ __nv_bfloat16 g_wgl[E_EXP * D_DIM];    // pre-split weights (lo)

// ---------------- helpers ----------------
__device__ __forceinline__ void mma_bf16(float c[4], uint32_t a0, uint32_t a1, uint32_t a2, uint32_t a3,
                                         uint32_t b0, uint32_t b1) {
    asm volatile(
        "mma.sync.aligned.m16n8k16.row.col.f32.bf16.bf16.f32 "
        "{%0,%1,%2,%3}, {%4,%5,%6,%7}, {%8,%9}, {%0,%1,%2,%3};"
        : "+f"(c[0]), "+f"(c[1]), "+f"(c[2]), "+f"(c[3])
        : "r"(a0), "r"(a1), "r"(a2), "r"(a3), "r"(b0), "r"(b1));
}
__device__ __forceinline__ void split_bf16(float f, uint16_t& h, uint16_t& l) {
    __nv_bfloat16 bh = __float2bfloat16(f);
    float rem = f - __bfloat162float(bh);
    __nv_bfloat16 bl = __float2bfloat16(rem);
    h = __bfloat16_as_ushort(bh);
    l = __bfloat16_as_ushort(bl);
}
__device__ __forceinline__ uint64_t pack4(uint16_t a, uint16_t b, uint16_t c, uint16_t d) {
    return (uint64_t)a | ((uint64_t)b << 16) | ((uint64_t)c << 32) | ((uint64_t)d << 48);
}

// ================= K-zero: output zeroing (separate kernel -> tiny reg footprint,
//                   co-resides with gemm CTAs when run on a forked graph branch) =================
__global__ void __launch_bounds__(512) zero_kernel(float* __restrict__ out, long long out_elems) {
    const long long total4 = out_elems >> 2;
    const long long per    = (total4 + gridDim.x - 1) / gridDim.x;
    const long long beg    = (long long)blockIdx.x * per;
    const long long end    = (beg + per < total4) ? beg + per : total4;
    float4* o4 = (float4*)out;
    const float4 z = make_float4(0.f, 0.f, 0.f, 0.f);
    for (long long i = beg + threadIdx.x; i < end; i += 512) o4[i] = z;
    if (blockIdx.x == 0 && threadIdx.x == 0)
        for (long long i = total4 * 4; i < out_elems; i++) out[i] = 0.f;
}

// ================= K0: pre-split wg into bf16 hi/lo =================
__global__ void __launch_bounds__(256) split_wg_kernel(const float* __restrict__ wg) {
    const int i = (blockIdx.x * 256 + threadIdx.x) * 4;   // 128 x 256 x 4 = 131072
    float4 v = *(const float4*)(wg + i);
    uint16_t h0, l0, h1, l1, h2, l2, h3, l3;
    split_bf16(v.x, h0, l0); split_bf16(v.y, h1, l1);
    split_bf16(v.z, h2, l2); split_bf16(v.w, h3, l3);
    ((uint64_t*)g_wgh)[i >> 2] = pack4(h0, h1, h2, h3);
    ((uint64_t*)g_wgl)[i >> 2] = pack4(l0, l1, l2, l3);
}

// ================= K1: HMMA GEMM (K-split warp groups) + softmax (round-12 form) =================
// 128 CTAs x 512 threads. CTA tile: 64 tokens x 64 experts.
#define KC     64
#define NCH_G  16                   // chunks per warp group
#define SROWH  72                   // padded row: 72 bf16 = 144B
#define TILE_B (64 * SROWH * 2)     // 9216 B per tile
#define OFF_AH 0
#define OFF_AL (TILE_B)
#define OFF_BH (2 * TILE_B)
#define OFF_BL (3 * TILE_B)
#define BUFSET (4 * TILE_B)         // 36864 per group
#define SM_DYN (2 * BUFSET)         // 73728

__global__ void __launch_bounds__(512) gemm_mma_kernel(const float* __restrict__ x) {
    extern __shared__ __align__(16) char smbuf[];

    const int tid  = threadIdx.x;
    const int lane = tid & 31;
    const int w    = tid >> 5;
    const int g    = w >> 3;            // warp group 0/1 (K-split)
    const int wg_  = w & 7;
    const int gtid = tid & 255;
    const int m0   = blockIdx.x * 64;
    const int M0   = (wg_ & 3) * 16;
    const int N0   = (wg_ >> 2) * 32;

    int rr[4], cc[4];
#pragma unroll
    for (int t = 0; t < 4; t++) { int f = gtid + t * 256; rr[t] = f >> 4; cc[t] = (f & 15) * 4; }
    int br[2], b8[2];
#pragma unroll
    for (int t = 0; t < 2; t++) { int u = gtid + t * 256; br[t] = u >> 3; b8[t] = u & 7; }

    char* mybuf = smbuf + g * BUFSET;
    const uint32_t* AH32 = (const uint32_t*)(mybuf + OFF_AH);
    const uint32_t* AL32 = (const uint32_t*)(mybuf + OFF_AL);
    const uint32_t* BH32 = (const uint32_t*)(mybuf + OFF_BH);
    const uint32_t* BL32 = (const uint32_t*)(mybuf + OFF_BL);
    const uint4* WH4 = (const uint4*)g_wgh;
    const uint4* WL4 = (const uint4*)g_wgl;

    float acc[4][4];
#pragma unroll
    for (int nt = 0; nt < 4; nt++)
#pragma unroll
        for (int j = 0; j < 4; j++) acc[nt][j] = 0.0f;

    float4 av[4];
    uint4  bvh[2], bvl[2];
    {
        const int kc = g * KC;
#pragma unroll
        for (int t = 0; t < 4; t++)
            av[t] = *(const float4*)(x + (size_t)(m0 + rr[t]) * D_DIM + kc + cc[t]);
#pragma unroll
        for (int t = 0; t < 2; t++) {
            bvh[t] = WH4[br[t] * (D_DIM / 8) + (kc >> 3) + b8[t]];
            bvl[t] = WL4[br[t] * (D_DIM / 8) + (kc >> 3) + b8[t]];
        }
    }

    for (int it = 0; it < NCH_G; it++) {
#pragma unroll
        for (int t = 0; t < 4; t++) {
            uint16_t h0, l0, h1, l1, h2, l2, h3, l3;
            const uint32_t off = (uint32_t)(rr[t] * SROWH + cc[t]) * 2;
            split_bf16(av[t].x, h0, l0); split_bf16(av[t].y, h1, l1);
            split_bf16(av[t].z, h2, l2); split_bf16(av[t].w, h3, l3);
            *(uint64_t*)(mybuf + OFF_AH + off) = pack4(h0, h1, h2, h3);
            *(uint64_t*)(mybuf + OFF_AL + off) = pack4(l0, l1, l2, l3);
        }
#pragma unroll
        for (int t = 0; t < 2; t++) {
            const uint32_t off = (uint32_t)(br[t] * SROWH) * 2 + b8[t] * 16;
            *(uint4*)(mybuf + OFF_BH + off) = bvh[t];
            *(uint4*)(mybuf + OFF_BL + off) = bvl[t];
        }
        __syncthreads();

        if (it + 1 < NCH_G) {
            const int kc = (2 * (it + 1) + g) * KC;
#pragma unroll
            for (int t = 0; t < 4; t++)
                av[t] = *(const float4*)(x + (size_t)(m0 + rr[t]) * D_DIM + kc + cc[t]);
#pragma unroll
            for (int t = 0; t < 2; t++) {
                bvh[t] = WH4[br[t] * (D_DIM / 8) + (kc >> 3) + b8[t]];
                bvl[t] = WL4[br[t] * (D_DIM / 8) + (kc >> 3) + b8[t]];
            }
        }

#pragma unroll
        for (int ks = 0; ks < 4; ks++) {
            const int kq = ks * 16 + (lane & 3) * 2;
            const int mA = M0 + (lane >> 2);
            const uint32_t ah0 = AH32[(mA * SROWH + kq) >> 1];
            const uint32_t ah1 = AH32[((mA + 8) * SROWH + kq) >> 1];
            const uint32_t ah2 = AH32[(mA * SROWH + kq + 8) >> 1];
            const uint32_t ah3 = AH32[((mA + 8) * SROWH + kq + 8) >> 1];
            const uint32_t al0 = AL32[(mA * SROWH + kq) >> 1];
            const uint32_t al1 = AL32[((mA + 8) * SROWH + kq) >> 1];
            const uint32_t al2 = AL32[(mA * SROWH + kq + 8) >> 1];
            const uint32_t al3 = AL32[((mA + 8) * SROWH + kq + 8) >> 1];
#pragma unroll
            for (int nt = 0; nt < 4; nt++) {
                const int nB = N0 + nt * 8 + (lane >> 2);
                const uint32_t bh0 = BH32[(nB * SROWH + kq) >> 1];
                const uint32_t bh1 = BH32[(nB * SROWH + kq + 8) >> 1];
                const uint32_t bl0 = BL32[(nB * SROWH + kq) >> 1];
                const uint32_t bl1 = BL32[(nB * SROWH + kq + 8) >> 1];
                mma_bf16(acc[nt], ah0, ah1, ah2, ah3, bh0, bh1);
                mma_bf16(acc[nt], ah0, ah1, ah2, ah3, bl0, bl1);
                mma_bf16(acc[nt], al0, al1, al2, al3, bh0, bh1);
                mma_bf16(acc[nt], al0, al1, al2, al3, bl0, bl1);
            }
        }
        __syncthreads();
    }

    // ---------- combine groups + softmax + rank/hist epilogue ----------
    float* Ls  = (float*)smbuf;            // [64][65]
    float* pg  = Ls + 64 * 65;             // [64][65]
    float* red = pg + 64 * 65;             // [8][64]
    int*   hw  = (int*)(red + 8 * 64);     // [2][64]

    const int r0 = M0 + (lane >> 2);
    const int cb = (lane & 3) * 2;
    if (g == 0) {
#pragma unroll
        for (int nt = 0; nt < 4; nt++) {
            const int c0 = N0 + nt * 8 + cb;
            Ls[r0 * 65 + c0]           = acc[nt][0];
            Ls[r0 * 65 + c0 + 1]       = acc[nt][1];
            Ls[(r0 + 8) * 65 + c0]     = acc[nt][2];
            Ls[(r0 + 8) * 65 + c0 + 1] = acc[nt][3];
        }
    }
    __syncthreads();
    if (g == 1) {
#pragma unroll
        for (int nt = 0; nt < 4; nt++) {
            const int c0 = N0 + nt * 8 + cb;
            Ls[r0 * 65 + c0]           += acc[nt][0];
            Ls[r0 * 65 + c0 + 1]       += acc[nt][1];
            Ls[(r0 + 8) * 65 + c0]     += acc[nt][2];
            Ls[(r0 + 8) * 65 + c0 + 1] += acc[nt][3];
        }
    }
    __syncthreads();

    int mi = 0;
    if (tid < 64) {
        float mv = -3.4e38f;
#pragma unroll
        for (int e = 0; e < 64; e++) {
            float v = Ls[tid * 65 + e];
            if (v > mv) { mv = v; mi = e; }     // first-occurrence argmax
        }
        float sum = 0.0f;
        float ev[64];
#pragma unroll
        for (int e = 0; e < 64; e++) { ev[e] = expf(Ls[tid * 65 + e] - mv); sum += ev[e]; }
        const float inv = 1.0f / sum;
        g_idx[m0 + tid]   = mi;
        g_gate1[m0 + tid] = inv;
#pragma unroll
        for (int e = 0; e < 64; e++) pg[tid * 65 + e] = ev[e] * inv;
    }
    if (tid < 128) hw[tid] = 0;
    __syncthreads();

    int rank = 0;
    if (tid < 64) {
        unsigned mm = __match_any_sync(0xffffffffu, mi);
        rank = __popc(mm & ((1u << lane) - 1u));
        if (lane == __ffs(mm) - 1) hw[(tid >> 5) * 64 + mi] = __popc(mm);
    }
    __syncthreads();
    if (tid < 64) {
        if (tid >= 32) rank += hw[mi];
        g_rank[m0 + tid] = rank;
        g_cnt[blockIdx.x * 64 + tid] = hw[tid] + hw[64 + tid];
    }

    {
        const int e = tid & 63, r = tid >> 6;
        float s2 = 0.0f;
#pragma unroll
        for (int j = 0; j < 8; j++) s2 += pg[(r * 8 + j) * 65 + e];
        red[r * 64 + e] = s2;
    }
    __syncthreads();
    if (tid < 64) {
        float s = 0.0f;
#pragma unroll
        for (int r = 0; r < 8; r++) s += red[r * 64 + tid];
        g_partialGateSum[(size_t)blockIdx.x * 64 + tid] = s;
    }
}

// ================= K2: prefix + aux + scatter (1 block; zeros already done) =================
__global__ void __launch_bounds__(1024) scan_scatter_kernel(float* __restrict__ combine,
                                                            float* __restrict__ maskp,
                                                            float* __restrict__ lauxp) {
    __shared__ int   bases[128 * E_EXP];   // 32 KB: global base per (tile, expert)
    __shared__ int   ss[16 * E_EXP];
    __shared__ float ps[16 * E_EXP];
    __shared__ int   cntS[E_EXP];
    __shared__ float vals[E_EXP];

    const int tid = threadIdx.x;
    const int e = tid & 63, r = tid >> 6;       // 16 slices x 8 tiles

    // ---- prefetch token data for scatter (independent LDGs, high MLP) ----
    int eA[8], rkA[8];
    float gA[8];
#pragma unroll
    for (int j = 0; j < 8; j++) eA[j]  = g_idx[tid + j * 1024];
#pragma unroll
    for (int j = 0; j < 8; j++) rkA[j] = g_rank[tid + j * 1024];
#pragma unroll
    for (int j = 0; j < 8; j++) gA[j]  = g_gate1[tid + j * 1024];

    int c[8], pre[8];
    float p[8];
#pragma unroll
    for (int j = 0; j < 8; j++) c[j] = g_cnt[(r * 8 + j) * 64 + e];
#pragma unroll
    for (int j = 0; j < 8; j++) p[j] = g_partialGateSum[(size_t)(r * 8 + j) * 64 + e];

    int s = 0;
#pragma unroll
    for (int j = 0; j < 8; j++) { pre[j] = s; s += c[j]; }
    ss[r * 64 + e] = s;
    float fs = 0.0f;
#pragma unroll
    for (int j = 0; j < 8; j++) fs += p[j];
    ps[r * 64 + e] = fs;
    __syncthreads();

    if (tid < 64) {
        int running = 0;
        for (int rr = 0; rr < 16; rr++) {
            int t = ss[rr * 64 + tid];
            ss[rr * 64 + tid] = running;
            running += t;
        }
        cntS[tid] = running;
    }
    __syncthreads();

    const int base0 = ss[r * 64 + e];
#pragma unroll
    for (int j = 0; j < 8; j++) bases[(r * 8 + j) * 64 + e] = base0 + pre[j];

    if (tid < 64) {
        float me = 0.0f;
#pragma unroll
        for (int rr = 0; rr < 16; rr++) me += ps[rr * 64 + tid];
        me /= (float)S_TOK;
        float ce = (float)cntS[tid] / (float)S_TOK;
        vals[tid] = me * ce;
    }
    __syncthreads();

    // ---- scatter ----
#pragma unroll
    for (int j = 0; j < 8; j++) {
        const int stok = tid + j * 1024;
        const int ee   = eA[j];
        const int loc  = bases[(stok >> 6) * 64 + ee] + rkA[j];
        if (loc < CAP) {
            const size_t off = (size_t)stok * (E_EXP * CAP) + (size_t)ee * CAP + loc;
            combine[off] = gA[j];
            if (maskp) maskp[off] = 1.0f;
        }
    }

    if (tid == 0 && lauxp) {
        float a = 0.0f;
        for (int ee = 0; ee < E_EXP; ee++) a += vals[ee];
        lauxp[0] = a * (float)E_EXP;            // mean * E*E == sum * E
    }
}

// ---------------- stream/event handles for graph fork (static init; no device mem alloc) ----------------
namespace {
cudaStream_t g_s2     = nullptr;
cudaEvent_t  g_evFork = nullptr;
cudaEvent_t  g_evJoin = nullptr;
struct ForkInit {
    ForkInit() {
        if (cudaStreamCreateWithFlags(&g_s2, cudaStreamNonBlocking) != cudaSuccess) g_s2 = nullptr;
        if (cudaEventCreateWithFlags(&g_evFork, cudaEventDisableTiming) != cudaSuccess) g_evFork = nullptr;
        if (cudaEventCreateWithFlags(&g_evJoin, cudaEventDisableTiming) != cudaSuccess) g_evJoin = nullptr;
    }
};
ForkInit g_forkInit;
}

// ---------------- launch ----------------
extern "C" void kernel_launch(void* const* d_in, const int* in_sizes, int n_in,
                              void* d_out, int out_size) {
    const float* x  = (const float*)d_in[0];   // [S, D]
    const float* wg = (const float*)d_in[1];   // [E, D]
    float* out = (float*)d_out;

    const long long SEC = (long long)S_TOK * E_EXP * CAP;  // 67,108,864
    float* lauxp   = nullptr;
    float* combine = out;
    float* maskp   = nullptr;
    if ((long long)out_size >= 1 + 2 * SEC) {          // [l_aux, combine, mask]
        lauxp = out; combine = out + 1; maskp = out + 1 + SEC;
    } else if ((long long)out_size == 1 + SEC) {       // [l_aux, combine]
        lauxp = out; combine = out + 1;
    }

    cudaFuncSetAttribute(gemm_mma_kernel, cudaFuncAttributeMaxDynamicSharedMemorySize, SM_DYN);

    const bool forked = (g_s2 != nullptr) && (g_evFork != nullptr) && (g_evJoin != nullptr);

    if (forked) {
        // fork: zero kernel runs as a concurrent graph branch (separate kernel =>
        // small reg footprint => zero blocks co-reside with gemm CTAs on every SM)
        cudaEventRecord(g_evFork, 0);
        cudaStreamWaitEvent(g_s2, g_evFork, 0);
        zero_kernel<<<1024, 512, 0, g_s2>>>(out, (long long)out_size);
        cudaEventRecord(g_evJoin, g_s2);
    } else {
        zero_kernel<<<1024, 512>>>(out, (long long)out_size);
    }

    split_wg_kernel<<<128, 256>>>(wg);
    gemm_mma_kernel<<<128, 512, SM_DYN>>>(x);

    if (forked) cudaStreamWaitEvent(0, g_evJoin, 0);   // join before touching out
    scan_scatter_kernel<<<1, 1024>>>(combine, maskp, lauxp);
}

// round 17
// speedup vs baseline: 1.1791x; 1.1755x over previous
#include <cuda_runtime.h>
#include <cuda_bf16.h>
#include <cstdint>

#define S_TOK 8192
#define D_DIM 2048
#define E_EXP 64
#define CAP   128

// ---------------- scratch ----------------
__device__ int   g_idx[S_TOK];
__device__ float g_gate1[S_TOK];
__device__ int   g_rank[S_TOK];                   // intra-tile rank within expert queue
__device__ int   g_cnt[128 * E_EXP];              // per-tile expert histogram
__device__ int   g_base[128 * E_EXP];             // global exclusive prefix per (tile, expert)
__device__ float g_partialGateSum[128 * E_EXP];   // per-tile softmax expert sums
__device__ __nv_bfloat16 g_wgh[E_EXP * D_DIM];    // pre-split weights (hi)
__device__ __nv_bfloat16 g_wgl[E_EXP * D_DIM];    // pre-split weights (lo)

// ---------------- helpers ----------------
__device__ __forceinline__ void mma_bf16(float c[4], uint32_t a0, uint32_t a1, uint32_t a2, uint32_t a3,
                                         uint32_t b0, uint32_t b1) {
    asm volatile(
        "mma.sync.aligned.m16n8k16.row.col.f32.bf16.bf16.f32 "
        "{%0,%1,%2,%3}, {%4,%5,%6,%7}, {%8,%9}, {%0,%1,%2,%3};"
        : "+f"(c[0]), "+f"(c[1]), "+f"(c[2]), "+f"(c[3])
        : "r"(a0), "r"(a1), "r"(a2), "r"(a3), "r"(b0), "r"(b1));
}
__device__ __forceinline__ void split_bf16(float f, uint16_t& h, uint16_t& l) {
    __nv_bfloat16 bh = __float2bfloat16(f);
    float rem = f - __bfloat162float(bh);
    __nv_bfloat16 bl = __float2bfloat16(rem);
    h = __bfloat16_as_ushort(bh);
    l = __bfloat16_as_ushort(bl);
}
__device__ __forceinline__ uint64_t pack4(uint16_t a, uint16_t b, uint16_t c, uint16_t d) {
    return (uint64_t)a | ((uint64_t)b << 16) | ((uint64_t)c << 32) | ((uint64_t)d << 48);
}

// ================= K0: pre-split wg into bf16 hi/lo =================
__global__ void __launch_bounds__(256) split_wg_kernel(const float* __restrict__ wg) {
    const int i = (blockIdx.x * 256 + threadIdx.x) * 4;   // 128 x 256 x 4 = 131072
    float4 v = *(const float4*)(wg + i);
    uint16_t h0, l0, h1, l1, h2, l2, h3, l3;
    split_bf16(v.x, h0, l0); split_bf16(v.y, h1, l1);
    split_bf16(v.z, h2, l2); split_bf16(v.w, h3, l3);
    ((uint64_t*)g_wgh)[i >> 2] = pack4(h0, h1, h2, h3);
    ((uint64_t*)g_wgl)[i >> 2] = pack4(l0, l1, l2, l3);
}

// ================= K1: fused HMMA GEMM + output zeroing (round-13 topology) =================
// Blocks 0..127  : gemm role (512 thr, 73.7KB smem)
// Blocks 128+    : zero role (streaming STG.128), backfills SMs as gemm drains
#define GEMM_BLOCKS 128
#define ZERO_BLOCKS 1024
#define KC     64
#define NCH_G  16                   // chunks per warp group
#define SROWH  72                   // padded row: 72 bf16 = 144B
#define TILE_B (64 * SROWH * 2)     // 9216 B per tile
#define OFF_AH 0
#define OFF_AL (TILE_B)
#define OFF_BH (2 * TILE_B)
#define OFF_BL (3 * TILE_B)
#define BUFSET (4 * TILE_B)         // 36864 per group
#define SM_DYN (2 * BUFSET)         // 73728

__global__ void __launch_bounds__(512) fused_gemm_zero_kernel(const float* __restrict__ x,
                                                              float* __restrict__ out,
                                                              long long out_elems) {
    // ---------- zero role ----------
    if (blockIdx.x >= GEMM_BLOCKS) {
        const long long zb = blockIdx.x - GEMM_BLOCKS;
        const long long total4 = out_elems >> 2;
        float4* o4 = (float4*)out;
        const float4 z = make_float4(0.f, 0.f, 0.f, 0.f);
        const long long stride = (long long)ZERO_BLOCKS * 512;
        for (long long i = zb * 512 + threadIdx.x; i < total4; i += stride)
            __stcs(o4 + i, z);
        if (zb == 0 && threadIdx.x == 0)
            for (long long i = total4 * 4; i < out_elems; i++) out[i] = 0.f;
        return;
    }

    // ---------- gemm role ----------
    extern __shared__ __align__(16) char smbuf[];

    const int tid  = threadIdx.x;
    const int lane = tid & 31;
    const int w    = tid >> 5;
    const int g    = w >> 3;            // warp group 0/1 (K-split)
    const int wg_  = w & 7;
    const int gtid = tid & 255;
    const int m0   = blockIdx.x * 64;
    const int M0   = (wg_ & 3) * 16;
    const int N0   = (wg_ >> 2) * 32;

    int rr[4], cc[4];
#pragma unroll
    for (int t = 0; t < 4; t++) { int f = gtid + t * 256; rr[t] = f >> 4; cc[t] = (f & 15) * 4; }
    int br[2], b8[2];
#pragma unroll
    for (int t = 0; t < 2; t++) { int u = gtid + t * 256; br[t] = u >> 3; b8[t] = u & 7; }

    char* mybuf = smbuf + g * BUFSET;
    const uint32_t* AH32 = (const uint32_t*)(mybuf + OFF_AH);
    const uint32_t* AL32 = (const uint32_t*)(mybuf + OFF_AL);
    const uint32_t* BH32 = (const uint32_t*)(mybuf + OFF_BH);
    const uint32_t* BL32 = (const uint32_t*)(mybuf + OFF_BL);
    const uint4* WH4 = (const uint4*)g_wgh;
    const uint4* WL4 = (const uint4*)g_wgl;

    float acc[4][4];
#pragma unroll
    for (int nt = 0; nt < 4; nt++)
#pragma unroll
        for (int j = 0; j < 4; j++) acc[nt][j] = 0.0f;

    float4 av[4];
    uint4  bvh[2], bvl[2];
    {
        const int kc = g * KC;
#pragma unroll
        for (int t = 0; t < 4; t++)
            av[t] = *(const float4*)(x + (size_t)(m0 + rr[t]) * D_DIM + kc + cc[t]);
#pragma unroll
        for (int t = 0; t < 2; t++) {
            bvh[t] = WH4[br[t] * (D_DIM / 8) + (kc >> 3) + b8[t]];
            bvl[t] = WL4[br[t] * (D_DIM / 8) + (kc >> 3) + b8[t]];
        }
    }

    for (int it = 0; it < NCH_G; it++) {
#pragma unroll
        for (int t = 0; t < 4; t++) {
            uint16_t h0, l0, h1, l1, h2, l2, h3, l3;
            const uint32_t off = (uint32_t)(rr[t] * SROWH + cc[t]) * 2;
            split_bf16(av[t].x, h0, l0); split_bf16(av[t].y, h1, l1);
            split_bf16(av[t].z, h2, l2); split_bf16(av[t].w, h3, l3);
            *(uint64_t*)(mybuf + OFF_AH + off) = pack4(h0, h1, h2, h3);
            *(uint64_t*)(mybuf + OFF_AL + off) = pack4(l0, l1, l2, l3);
        }
#pragma unroll
        for (int t = 0; t < 2; t++) {
            const uint32_t off = (uint32_t)(br[t] * SROWH) * 2 + b8[t] * 16;
            *(uint4*)(mybuf + OFF_BH + off) = bvh[t];
            *(uint4*)(mybuf + OFF_BL + off) = bvl[t];
        }
        __syncthreads();

        if (it + 1 < NCH_G) {
            const int kc = (2 * (it + 1) + g) * KC;
#pragma unroll
            for (int t = 0; t < 4; t++)
                av[t] = *(const float4*)(x + (size_t)(m0 + rr[t]) * D_DIM + kc + cc[t]);
#pragma unroll
            for (int t = 0; t < 2; t++) {
                bvh[t] = WH4[br[t] * (D_DIM / 8) + (kc >> 3) + b8[t]];
                bvl[t] = WL4[br[t] * (D_DIM / 8) + (kc >> 3) + b8[t]];
            }
        }

        // ---- MMA: 4 k16-steps x 4 n8-tiles x 3 split terms (hh + hl + lh) ----
        // (xl*wl term dropped: contributes O(2^-18) relative, same order as the
        //  split residual already neglected -> accuracy unchanged)
#pragma unroll
        for (int ks = 0; ks < 4; ks++) {
            const int kq = ks * 16 + (lane & 3) * 2;
            const int mA = M0 + (lane >> 2);
            const uint32_t ah0 = AH32[(mA * SROWH + kq) >> 1];
            const uint32_t ah1 = AH32[((mA + 8) * SROWH + kq) >> 1];
            const uint32_t ah2 = AH32[(mA * SROWH + kq + 8) >> 1];
            const uint32_t ah3 = AH32[((mA + 8) * SROWH + kq + 8) >> 1];
            const uint32_t al0 = AL32[(mA * SROWH + kq) >> 1];
            const uint32_t al1 = AL32[((mA + 8) * SROWH + kq) >> 1];
            const uint32_t al2 = AL32[(mA * SROWH + kq + 8) >> 1];
            const uint32_t al3 = AL32[((mA + 8) * SROWH + kq + 8) >> 1];
#pragma unroll
            for (int nt = 0; nt < 4; nt++) {
                const int nB = N0 + nt * 8 + (lane >> 2);
                const uint32_t bh0 = BH32[(nB * SROWH + kq) >> 1];
                const uint32_t bh1 = BH32[(nB * SROWH + kq + 8) >> 1];
                const uint32_t bl0 = BL32[(nB * SROWH + kq) >> 1];
                const uint32_t bl1 = BL32[(nB * SROWH + kq + 8) >> 1];
                mma_bf16(acc[nt], ah0, ah1, ah2, ah3, bh0, bh1);
                mma_bf16(acc[nt], ah0, ah1, ah2, ah3, bl0, bl1);
                mma_bf16(acc[nt], al0, al1, al2, al3, bh0, bh1);
            }
        }
        __syncthreads();
    }

    // ---------- combine groups + softmax + rank/hist epilogue ----------
    float* Ls  = (float*)smbuf;            // [64][65]
    float* pg  = Ls + 64 * 65;             // [64][65]
    float* red = pg + 64 * 65;             // [8][64]
    int*   hw  = (int*)(red + 8 * 64);     // [2][64]

    const int r0 = M0 + (lane >> 2);
    const int cb = (lane & 3) * 2;
    if (g == 0) {
#pragma unroll
        for (int nt = 0; nt < 4; nt++) {
            const int c0 = N0 + nt * 8 + cb;
            Ls[r0 * 65 + c0]           = acc[nt][0];
            Ls[r0 * 65 + c0 + 1]       = acc[nt][1];
            Ls[(r0 + 8) * 65 + c0]     = acc[nt][2];
            Ls[(r0 + 8) * 65 + c0 + 1] = acc[nt][3];
        }
    }
    __syncthreads();
    if (g == 1) {
#pragma unroll
        for (int nt = 0; nt < 4; nt++) {
            const int c0 = N0 + nt * 8 + cb;
            Ls[r0 * 65 + c0]           += acc[nt][0];
            Ls[r0 * 65 + c0 + 1]       += acc[nt][1];
            Ls[(r0 + 8) * 65 + c0]     += acc[nt][2];
            Ls[(r0 + 8) * 65 + c0 + 1] += acc[nt][3];
        }
    }
    __syncthreads();

    int mi = 0;
    if (tid < 64) {
        float mv = -3.4e38f;
#pragma unroll
        for (int e = 0; e < 64; e++) {
            float v = Ls[tid * 65 + e];
            if (v > mv) { mv = v; mi = e; }     // first-occurrence argmax
        }
        float sum = 0.0f;
        float ev[64];
#pragma unroll
        for (int e = 0; e < 64; e++) { ev[e] = expf(Ls[tid * 65 + e] - mv); sum += ev[e]; }
        const float inv = 1.0f / sum;
        g_idx[m0 + tid]   = mi;
        g_gate1[m0 + tid] = inv;
#pragma unroll
        for (int e = 0; e < 64; e++) pg[tid * 65 + e] = ev[e] * inv;
    }
    if (tid < 128) hw[tid] = 0;
    __syncthreads();

    int rank = 0;
    if (tid < 64) {
        unsigned mm = __match_any_sync(0xffffffffu, mi);
        rank = __popc(mm & ((1u << lane) - 1u));
        if (lane == __ffs(mm) - 1) hw[(tid >> 5) * 64 + mi] = __popc(mm);
    }
    __syncthreads();
    if (tid < 64) {
        if (tid >= 32) rank += hw[mi];
        g_rank[m0 + tid] = rank;
        g_cnt[blockIdx.x * 64 + tid] = hw[tid] + hw[64 + tid];
    }

    {
        const int e = tid & 63, r = tid >> 6;
        float s2 = 0.0f;
#pragma unroll
        for (int j = 0; j < 8; j++) s2 += pg[(r * 8 + j) * 65 + e];
        red[r * 64 + e] = s2;
    }
    __syncthreads();
    if (tid < 64) {
        float s = 0.0f;
#pragma unroll
        for (int r = 0; r < 8; r++) s += red[r * 64 + tid];
        g_partialGateSum[(size_t)blockIdx.x * 64 + tid] = s;
    }
}

// ================= K2: cross-tile prefix + aux loss (1 block) =================
__global__ void __launch_bounds__(1024) scan_base_kernel(float* __restrict__ lauxp) {
    __shared__ int   ss[16 * E_EXP];
    __shared__ float ps[16 * E_EXP];
    __shared__ int   cntS[E_EXP];
    __shared__ float vals[E_EXP];

    const int tid = threadIdx.x;
    const int e = tid & 63, r = tid >> 6;       // 16 slices x 8 tiles

    int c[8], pre[8];
    float p[8];
#pragma unroll
    for (int j = 0; j < 8; j++) c[j] = g_cnt[(r * 8 + j) * 64 + e];
#pragma unroll
    for (int j = 0; j < 8; j++) p[j] = g_partialGateSum[(size_t)(r * 8 + j) * 64 + e];

    int s = 0;
#pragma unroll
    for (int j = 0; j < 8; j++) { pre[j] = s; s += c[j]; }
    ss[r * 64 + e] = s;
    float fs = 0.0f;
#pragma unroll
    for (int j = 0; j < 8; j++) fs += p[j];
    ps[r * 64 + e] = fs;
    __syncthreads();

    if (tid < 64) {
        int running = 0;
        for (int rr = 0; rr < 16; rr++) {
            int t = ss[rr * 64 + tid];
            ss[rr * 64 + tid] = running;
            running += t;
        }
        cntS[tid] = running;
    }
    __syncthreads();

    const int base0 = ss[r * 64 + e];
#pragma unroll
    for (int j = 0; j < 8; j++) g_base[(r * 8 + j) * 64 + e] = base0 + pre[j];

    if (tid < 64) {
        float me = 0.0f;
#pragma unroll
        for (int rr = 0; rr < 16; rr++) me += ps[rr * 64 + tid];
        me /= (float)S_TOK;
        float ce = (float)cntS[tid] / (float)S_TOK;
        vals[tid] = me * ce;
    }
    __syncthreads();
    if (tid == 0 && lauxp) {
        float a = 0.0f;
        for (int ee = 0; ee < E_EXP; ee++) a += vals[ee];
        lauxp[0] = a * (float)E_EXP;            // mean * E*E == sum * E
    }
}

// ================= K3: scatter combine + mask (32 blocks, MLP-prefetched) =================
__global__ void __launch_bounds__(256) scatter_kernel(float* __restrict__ combine,
                                                      float* __restrict__ maskp) {
    const int s = blockIdx.x * 256 + threadIdx.x;
    // independent loads first (MLP)
    const int   e  = g_idx[s];
    const int   rk = g_rank[s];
    const float gv = g_gate1[s];
    const int loc = g_base[(s >> 6) * 64 + e] + rk;
    if (loc < CAP) {
        const size_t off = (size_t)s * (E_EXP * CAP) + (size_t)e * CAP + loc;
        combine[off] = gv;
        if (maskp) maskp[off] = 1.0f;
    }
}

// ---------------- launch ----------------
extern "C" void kernel_launch(void* const* d_in, const int* in_sizes, int n_in,
                              void* d_out, int out_size) {
    const float* x  = (const float*)d_in[0];   // [S, D]
    const float* wg = (const float*)d_in[1];   // [E, D]
    float* out = (float*)d_out;

    const long long SEC = (long long)S_TOK * E_EXP * CAP;  // 67,108,864
    float* lauxp   = nullptr;
    float* combine = out;
    float* maskp   = nullptr;
    if ((long long)out_size >= 1 + 2 * SEC) {          // [l_aux, combine, mask]
        lauxp = out; combine = out + 1; maskp = out + 1 + SEC;
    } else if ((long long)out_size == 1 + SEC) {       // [l_aux, combine]
        lauxp = out; combine = out + 1;
    }

    cudaFuncSetAttribute(fused_gemm_zero_kernel, cudaFuncAttributeMaxDynamicSharedMemorySize, SM_DYN);

    split_wg_kernel<<<128, 256>>>(wg);
    fused_gemm_zero_kernel<<<GEMM_BLOCKS + ZERO_BLOCKS, 512, SM_DYN>>>(x, out, (long long)out_size);
    scan_base_kernel<<<1, 1024>>>(lauxp);
    scatter_kernel<<<S_TOK / 256, 256>>>(combine, maskp);
}